// round 14
// baseline (speedup 1.0000x reference)
#include <cuda_runtime.h>
#include <cuda_bf16.h>
#include <cuda_fp16.h>
#include <cstdint>

// Problem constants
#define B_  8
#define LQ_ 8192
#define LK_ 1024
#define NF_ 64
#define NTILE 16          // key tiles of 64
#define LOG2E 1.4426950408889634f

// ===========================================================================
// Scratch (device globals: allocation-free per harness rules)
// ===========================================================================
__device__ __align__(256) __half g_kh[B_ * LK_ * NF_];
__device__ __align__(256) __half g_kl[B_ * LK_ * NF_];
__device__ __align__(256) __half g_vth[B_ * NF_ * LK_];  // V^T: [b][feat][key]

// ===========================================================================
// Generic-PTX helpers (sm_75..90 class: mma.sync + cp.async + ldmatrix)
// ===========================================================================
__device__ __forceinline__ uint32_t smem_u32(const void* p) {
    uint32_t a;
    asm("{ .reg .u64 t; cvta.to.shared.u64 t, %1; cvt.u32.u64 %0, t; }" : "=r"(a) : "l"(p));
    return a;
}
__device__ __forceinline__ void cp16(uint32_t dst, const void* src) {
    asm volatile("cp.async.cg.shared.global [%0], [%1], 16;" :: "r"(dst), "l"(src) : "memory");
}
#define CP_COMMIT() asm volatile("cp.async.commit_group;" ::: "memory")
#define CP_WAIT0()  asm volatile("cp.async.wait_group 0;" ::: "memory")

// D += A * B  (m16n8k16, A row-major, B col-major, fp16 in, f32 accum)
__device__ __forceinline__ void mma16816h(float* d, const uint32_t* a, const uint32_t* b) {
    asm volatile(
        "mma.sync.aligned.m16n8k16.row.col.f32.f16.f16.f32 "
        "{%0,%1,%2,%3}, {%4,%5,%6,%7}, {%8,%9}, {%0,%1,%2,%3};"
        : "+f"(d[0]), "+f"(d[1]), "+f"(d[2]), "+f"(d[3])
        : "r"(a[0]), "r"(a[1]), "r"(a[2]), "r"(a[3]), "r"(b[0]), "r"(b[1]));
}
#define LDMX4(r, addr)                                                      \
    asm volatile("ldmatrix.sync.aligned.m8n8.x4.shared.b16 {%0,%1,%2,%3}, [%4];" \
        : "=r"((r)[0]), "=r"((r)[1]), "=r"((r)[2]), "=r"((r)[3]) : "r"(addr))

__device__ __forceinline__ uint32_t pack2h(float x, float y) {
    __half2 t = __floats2half2_rn(x, y);
    return *(uint32_t*)&t;
}

// ===========================================================================
// Fused K + V projection: fp32 compute, split fp16 output.
// K: hi+lo row-major. V: hi only, transposed [b][feat][key].
// ===========================================================================
__global__ __launch_bounds__(256) void projkv_kernel(
    const float* __restrict__ kv,
    const float* __restrict__ Wk, const float* __restrict__ Wv,
    __half* __restrict__ okh, __half* __restrict__ okl,
    __half* __restrict__ ovh)
{
    __shared__ float sWk[NF_ * NF_];
    __shared__ float sWv[NF_ * NF_];
    __shared__ float sIn[64 * NF_];
    const int tid = threadIdx.x;
    const long long r0 = (long long)blockIdx.x * 64;

    #pragma unroll
    for (int j = 0; j < 4; j++) {
        ((float4*)sWk)[tid + 256 * j] = ((const float4*)Wk)[tid + 256 * j];
        ((float4*)sWv)[tid + 256 * j] = ((const float4*)Wv)[tid + 256 * j];
        ((float4*)sIn)[tid + 256 * j] = ((const float4*)(kv + r0 * NF_))[tid + 256 * j];
    }
    __syncthreads();

    const int rq = tid >> 4, tx = tid & 15;

    #pragma unroll
    for (int which = 0; which < 2; which++) {
        const float* sW = which ? sWv : sWk;
        float acc[4][4];
        #pragma unroll
        for (int i = 0; i < 4; i++)
            #pragma unroll
            for (int j = 0; j < 4; j++) acc[i][j] = 0.f;

        #pragma unroll
        for (int d4 = 0; d4 < 16; d4++) {
            float4 av[4], wv[4];
            #pragma unroll
            for (int i = 0; i < 4; i++) av[i] = *(const float4*)&sIn[(rq * 4 + i) * NF_ + d4 * 4];
            #pragma unroll
            for (int dd = 0; dd < 4; dd++) wv[dd] = *(const float4*)&sW[(d4 * 4 + dd) * NF_ + tx * 4];
            #pragma unroll
            for (int i = 0; i < 4; i++) {
                const float* af = (const float*)&av[i];
                #pragma unroll
                for (int dd = 0; dd < 4; dd++) {
                    const float* wf = (const float*)&wv[dd];
                    #pragma unroll
                    for (int j = 0; j < 4; j++)
                        acc[i][j] = fmaf(af[dd], wf[j], acc[i][j]);
                }
            }
        }

        #pragma unroll
        for (int i = 0; i < 4; i++) {
            const long long row = r0 + rq * 4 + i;
            if (which == 0) {
                uint2 hw, lw;
                __half h0 = __float2half_rn(acc[i][0]), h1 = __float2half_rn(acc[i][1]);
                __half h2 = __float2half_rn(acc[i][2]), h3 = __float2half_rn(acc[i][3]);
                hw.x = pack2h(acc[i][0], acc[i][1]);
                hw.y = pack2h(acc[i][2], acc[i][3]);
                lw.x = pack2h(acc[i][0] - __half2float(h0), acc[i][1] - __half2float(h1));
                lw.y = pack2h(acc[i][2] - __half2float(h2), acc[i][3] - __half2float(h3));
                *(uint2*)(okh + row * NF_ + tx * 4) = hw;
                *(uint2*)(okl + row * NF_ + tx * 4) = lw;
            } else {
                const long long b   = row >> 10;
                const long long key = row & 1023;
                #pragma unroll
                for (int j = 0; j < 4; j++) {
                    const long long idx = (b * NF_ + (tx * 4 + j)) * LK_ + key;
                    ovh[idx] = __float2half_rn(acc[i][j]);
                }
            }
        }
    }
}

// ===========================================================================
// Fused q-proj + flash attention via fp16 mma.sync.
// q is pre-scaled by log2(e) so softmax runs in exp2 domain.
// S = qh*kh + qh*kl + ql*kh (3 terms); PV = ph*vh (1 term, fp16).
// Online softmax: ONE max/rescale/exp pass per 64-key tile.
// CTA: 256 threads = 8 warps; warp w owns query rows w*16..w*16+15.
// Smem (80KB/CTA, 2 CTAs/SM):
//   [0,16K)   QH fragments [kc][tid] 16B;  [16,32K) QL fragments
//   [32,56K)  buffer 0 (KH/KL/VH 8KB each);  [56,80K) buffer 1
//   prologue reuse: x staging at 32K (32KB), Wq at 64K (16KB)
// ===========================================================================
#define OFF_QHF 0
#define OFF_QLF 16384
#define OFF_BUF 32768
#define BUF_BYTES 24576
#define OFF_KH 0
#define OFF_KL 8192
#define OFF_VH 16384
#define SMEM_TOTAL 81920

__global__ __launch_bounds__(256, 2) void attn_fused_kernel(
    const float* __restrict__ x, const float* __restrict__ Wq,
    const __half* __restrict__ kh, const __half* __restrict__ kl,
    const __half* __restrict__ vth,
    float* __restrict__ out)
{
    extern __shared__ char smem[];
    const uint32_t sb = smem_u32(smem);
    const int tid  = threadIdx.x;
    const int w    = tid >> 5;
    const int lane = tid & 31;
    const int b    = blockIdx.x >> 6;
    const int q0   = (blockIdx.x & 63) * 128;

    // ---------------- prologue: q = (x * Wq) * log2e, split to frag smem ----
    {
        const char* gx = (const char*)(x + ((size_t)b * LQ_ + q0) * NF_);
        #pragma unroll
        for (int j = 0; j < 8; j++) {
            const int c = tid + 256 * j;               // 0..2047 (x: 32KB)
            cp16(sb + OFF_BUF + (uint32_t)c * 16, gx + (size_t)c * 16);
        }
        #pragma unroll
        for (int j = 0; j < 4; j++) {
            const int c = tid + 256 * j;               // 0..1023 (Wq: 16KB)
            cp16(sb + OFF_BUF + 32768 + (uint32_t)c * 16, (const char*)Wq + (size_t)c * 16);
        }
        CP_COMMIT();
        CP_WAIT0();
        __syncthreads();

        const float* sIn = (const float*)(smem + OFF_BUF);
        const float* sW  = (const float*)(smem + OFF_BUF + 32768);
        const int rq = tid >> 4, tx = tid & 15;

        #pragma unroll
        for (int rr = 0; rr < 2; rr++) {
            float acc[4][4];
            #pragma unroll
            for (int i = 0; i < 4; i++)
                #pragma unroll
                for (int j = 0; j < 4; j++) acc[i][j] = 0.f;

            #pragma unroll
            for (int d4 = 0; d4 < 16; d4++) {
                float4 av[4], wv[4];
                #pragma unroll
                for (int i = 0; i < 4; i++)
                    av[i] = *(const float4*)&sIn[(rr * 64 + rq * 4 + i) * NF_ + d4 * 4];
                #pragma unroll
                for (int dd = 0; dd < 4; dd++)
                    wv[dd] = *(const float4*)&sW[(d4 * 4 + dd) * NF_ + tx * 4];
                #pragma unroll
                for (int i = 0; i < 4; i++) {
                    const float* af = (const float*)&av[i];
                    #pragma unroll
                    for (int dd = 0; dd < 4; dd++) {
                        const float* wf = (const float*)&wv[dd];
                        #pragma unroll
                        for (int j = 0; j < 4; j++)
                            acc[i][j] = fmaf(af[dd], wf[j], acc[i][j]);
                    }
                }
            }
            // scale to exp2 domain, then split into fp16 hi/lo fragments
            #pragma unroll
            for (int i = 0; i < 4; i++) {
                const int row = rr * 64 + rq * 4 + i;
                #pragma unroll
                for (int j = 0; j < 4; j++) {
                    const int col = tx * 4 + j;
                    const float a = acc[i][j] * LOG2E;
                    const __half h = __float2half_rn(a);
                    const __half l = __float2half_rn(a - __half2float(h));
                    const int kc  = col >> 4;
                    const int c4  = col & 15;
                    const int idx = ((row >> 3) & 1) | ((c4 >> 3) << 1);
                    const int tf  = ((row >> 4) << 5) | (((row & 7) << 2) | ((c4 & 7) >> 1));
                    const uint32_t off = (uint32_t)(kc * 4096 + tf * 16 + idx * 4 + (c4 & 1) * 2);
                    *(__half*)(smem + OFF_QHF + off) = h;
                    *(__half*)(smem + OFF_QLF + off) = l;
                }
            }
        }
        __syncthreads();   // frags visible; staging areas now reusable
    }

    // ---- load persistent Q hi + lo fragments (conflict-free LDS.128) ----
    uint32_t qhf[4][4], qlf[4][4];
    #pragma unroll
    for (int kc = 0; kc < 4; kc++) {
        uint4 t0 = *(const uint4*)(smem + OFF_QHF + kc * 4096 + (size_t)tid * 16);
        qhf[kc][0] = t0.x; qhf[kc][1] = t0.y; qhf[kc][2] = t0.z; qhf[kc][3] = t0.w;
        uint4 t1 = *(const uint4*)(smem + OFF_QLF + kc * 4096 + (size_t)tid * 16);
        qlf[kc][0] = t1.x; qlf[kc][1] = t1.y; qlf[kc][2] = t1.z; qlf[kc][3] = t1.w;
    }

    // ---- K/V tile loader (cp.async, swizzled) ----
    const char* gkh = (const char*)(kh  + (size_t)b * LK_ * NF_);
    const char* gkl = (const char*)(kl  + (size_t)b * LK_ * NF_);
    const char* gvh = (const char*)(vth + (size_t)b * NF_ * LK_);

    auto load_tile = [&](int t, int buf) {
        const uint32_t bb = sb + OFF_BUF + (uint32_t)buf * BUF_BYTES;
        #pragma unroll
        for (int j = 0; j < 2; j++) {
            const int c  = tid + j * 256;          // 0..511
            const int r  = c >> 3, ch = c & 7;
            const uint32_t sw = (uint32_t)(r * 128 + ((ch * 16) ^ ((r & 7) << 4)));
            const size_t koff = ((size_t)(t * 64 + r) * NF_ + ch * 8) * 2;
            const size_t voff = ((size_t)r * LK_ + t * 64 + ch * 8) * 2;
            cp16(bb + OFF_KH + sw, gkh + koff);
            cp16(bb + OFF_KL + sw, gkl + koff);
            cp16(bb + OFF_VH + sw, gvh + voff);
        }
    };

    load_tile(0, 0);
    CP_COMMIT();

    float o_acc[8][4];
    #pragma unroll
    for (int n = 0; n < 8; n++)
        #pragma unroll
        for (int j = 0; j < 4; j++) o_acc[n][j] = 0.f;
    float l0 = 0.f, l1 = 0.f;
    float m0 = -1e30f, m1 = -1e30f;

    const int ln7 = lane & 7;
    const int c0  = lane >> 3;                 // 0..3 (chunk select for ldmatrix)
    const uint32_t krowoff = (uint32_t)(ln7 * 128 + ((c0 * 16) ^ (ln7 << 4)));
    const int vrow_base = ((lane >> 4) << 3) + ln7;
    const int vchunk_sel = (lane >> 3) & 1;

    for (int i = 0; i < NTILE; i++) {
        CP_WAIT0();                            // tile i landed
        __syncthreads();                       // + all warps done with iter i-1
        if (i + 1 < NTILE) { load_tile(i + 1, (i + 1) & 1); CP_COMMIT(); }

        const uint32_t bb  = sb + OFF_BUF + (uint32_t)(i & 1) * BUF_BYTES;
        const uint32_t bKh = bb + OFF_KH, bKl = bb + OFF_KL, bVh = bb + OFF_VH;

        // ---- S phase: all 8 n-tiles (64 keys), dense LDSM+HMMA ----
        float s8[8][4];
        #pragma unroll
        for (int nn = 0; nn < 8; nn++) {
            const uint32_t ka = (uint32_t)(nn * 1024) + krowoff;
            uint32_t kh8[8], kl8[8];
            LDMX4(kh8,     bKh + ka);
            LDMX4(kh8 + 4, (bKh + ka) ^ 64u);
            LDMX4(kl8,     bKl + ka);
            LDMX4(kl8 + 4, (bKl + ka) ^ 64u);
            float* s = s8[nn];
            s[0] = s[1] = s[2] = s[3] = 0.f;
            #pragma unroll
            for (int kc = 0; kc < 4; kc++) {
                mma16816h(s, qhf[kc], &kh8[2 * kc]);
                mma16816h(s, qhf[kc], &kl8[2 * kc]);
                mma16816h(s, qlf[kc], &kh8[2 * kc]);
            }
        }

        // ---- single softmax block per tile ----
        float t0 = fmaxf(s8[0][0], s8[0][1]);
        float t1 = fmaxf(s8[0][2], s8[0][3]);
        #pragma unroll
        for (int nn = 1; nn < 8; nn++) {
            t0 = fmaxf(t0, fmaxf(s8[nn][0], s8[nn][1]));
            t1 = fmaxf(t1, fmaxf(s8[nn][2], s8[nn][3]));
        }
        t0 = fmaxf(t0, __shfl_xor_sync(0xffffffffu, t0, 1));
        t0 = fmaxf(t0, __shfl_xor_sync(0xffffffffu, t0, 2));
        t1 = fmaxf(t1, __shfl_xor_sync(0xffffffffu, t1, 1));
        t1 = fmaxf(t1, __shfl_xor_sync(0xffffffffu, t1, 2));
        const float mn0 = fmaxf(m0, t0);
        const float mn1 = fmaxf(m1, t1);
        const int changed = (mn0 > m0) | (mn1 > m1);
        if (__any_sync(0xffffffffu, changed)) {
            const float sc0 = exp2f(m0 - mn0);
            const float sc1 = exp2f(m1 - mn1);
            m0 = mn0; m1 = mn1;
            l0 *= sc0; l1 *= sc1;
            #pragma unroll
            for (int n = 0; n < 8; n++) {
                o_acc[n][0] *= sc0; o_acc[n][1] *= sc0;
                o_acc[n][2] *= sc1; o_acc[n][3] *= sc1;
            }
        }

        // ---- exp2 + pack P (fp16) for the whole tile ----
        uint32_t ph[4][4];
        #pragma unroll
        for (int nn = 0; nn < 8; nn++) {
            const float p0 = exp2f(s8[nn][0] - m0);
            const float p1 = exp2f(s8[nn][1] - m0);
            const float p2 = exp2f(s8[nn][2] - m1);
            const float p3 = exp2f(s8[nn][3] - m1);
            l0 += p0 + p1;
            l1 += p2 + p3;
            const int tt = nn >> 1, h = nn & 1;
            ph[tt][h * 2 + 0] = pack2h(p0, p1);
            ph[tt][h * 2 + 1] = pack2h(p2, p3);
        }

        // ---- O += P * V (single fp16 term) ----
        #pragma unroll
        for (int tt = 0; tt < 4; tt++) {
            const int ch = 2 * tt + vchunk_sel;
            #pragma unroll
            for (int p = 0; p < 4; p++) {
                const int vrow = p * 16 + vrow_base;
                const uint32_t va = (uint32_t)(vrow * 128 + ((ch * 16) ^ (ln7 << 4)));
                uint32_t vh4[4];
                LDMX4(vh4, bVh + va);
                mma16816h(o_acc[2 * p],     ph[tt], &vh4[0]);
                mma16816h(o_acc[2 * p + 1], ph[tt], &vh4[2]);
            }
        }
    }

    // ---- finalize: reduce l over the 4-lane row group, divide, store ----
    l0 += __shfl_xor_sync(0xffffffffu, l0, 1);
    l0 += __shfl_xor_sync(0xffffffffu, l0, 2);
    l1 += __shfl_xor_sync(0xffffffffu, l1, 1);
    l1 += __shfl_xor_sync(0xffffffffu, l1, 2);
    const float inv0 = 1.f / l0;
    const float inv1 = 1.f / l1;

    const size_t gr0 = (size_t)b * LQ_ + q0 + w * 16 + (lane >> 2);
    const size_t gr1 = gr0 + 8;
    #pragma unroll
    for (int n = 0; n < 8; n++) {
        const int col = n * 8 + (lane & 3) * 2;
        float2 v0, v1;
        v0.x = o_acc[n][0] * inv0; v0.y = o_acc[n][1] * inv0;
        v1.x = o_acc[n][2] * inv1; v1.y = o_acc[n][3] * inv1;
        *(float2*)(out + gr0 * NF_ + col) = v0;
        *(float2*)(out + gr1 * NF_ + col) = v1;
    }
}

// ===========================================================================
// Launch. Inputs (metadata order): x[B,LQ,NF], kv[B,LK,NF], Wq, Wk, Wv.
// ===========================================================================
extern "C" void kernel_launch(void* const* d_in, const int* in_sizes, int n_in,
                              void* d_out, int out_size)
{
    const float* x  = (const float*)d_in[0];
    const float* kv = (const float*)d_in[1];
    const float* Wq = (const float*)d_in[2];
    const float* Wk = (const float*)d_in[3];
    const float* Wv = (const float*)d_in[4];
    float* out = (float*)d_out;

    __half *kh, *kl, *vth;
    cudaGetSymbolAddress((void**)&kh,  g_kh);
    cudaGetSymbolAddress((void**)&kl,  g_kl);
    cudaGetSymbolAddress((void**)&vth, g_vth);

    cudaFuncSetAttribute(attn_fused_kernel,
                         cudaFuncAttributeMaxDynamicSharedMemorySize, SMEM_TOTAL);

    projkv_kernel<<<(B_ * LK_) / 64, 256>>>(kv, Wk, Wv, kh, kl, vth);

    attn_fused_kernel<<<B_ * (LQ_ / 128), 256, SMEM_TOTAL>>>(x, Wq, kh, kl, vth, out);
}

// round 17
// speedup vs baseline: 1.0678x; 1.0678x over previous
#include <cuda_runtime.h>
#include <cuda_bf16.h>
#include <cuda_fp16.h>
#include <cstdint>

// Problem constants
#define B_  8
#define LQ_ 8192
#define LK_ 1024
#define NF_ 64
#define NTILE 16          // key tiles of 64
#define LOG2E 1.4426950408889634f

// ===========================================================================
// Scratch (device globals: allocation-free per harness rules)
// ===========================================================================
__device__ __align__(256) __half g_kh[B_ * LK_ * NF_];
__device__ __align__(256) __half g_kl[B_ * LK_ * NF_];
__device__ __align__(256) __half g_vth[B_ * NF_ * LK_];  // V^T: [b][feat][key]

// ===========================================================================
// Generic-PTX helpers (sm_75..90 class: mma.sync + cp.async + ldmatrix)
// ===========================================================================
__device__ __forceinline__ uint32_t smem_u32(const void* p) {
    uint32_t a;
    asm("{ .reg .u64 t; cvta.to.shared.u64 t, %1; cvt.u32.u64 %0, t; }" : "=r"(a) : "l"(p));
    return a;
}
__device__ __forceinline__ void cp16(uint32_t dst, const void* src) {
    asm volatile("cp.async.cg.shared.global [%0], [%1], 16;" :: "r"(dst), "l"(src) : "memory");
}
#define CP_COMMIT() asm volatile("cp.async.commit_group;" ::: "memory")
#define CP_WAIT0()  asm volatile("cp.async.wait_group 0;" ::: "memory")

// D += A * B  (m16n8k16, A row-major, B col-major, fp16 in, f32 accum)
__device__ __forceinline__ void mma16816h(float* d, const uint32_t* a, const uint32_t* b) {
    asm volatile(
        "mma.sync.aligned.m16n8k16.row.col.f32.f16.f16.f32 "
        "{%0,%1,%2,%3}, {%4,%5,%6,%7}, {%8,%9}, {%0,%1,%2,%3};"
        : "+f"(d[0]), "+f"(d[1]), "+f"(d[2]), "+f"(d[3])
        : "r"(a[0]), "r"(a[1]), "r"(a[2]), "r"(a[3]), "r"(b[0]), "r"(b[1]));
}
#define LDMX4(r, addr)                                                      \
    asm volatile("ldmatrix.sync.aligned.m8n8.x4.shared.b16 {%0,%1,%2,%3}, [%4];" \
        : "=r"((r)[0]), "=r"((r)[1]), "=r"((r)[2]), "=r"((r)[3]) : "r"(addr))

__device__ __forceinline__ uint32_t pack2h(float x, float y) {
    __half2 t = __floats2half2_rn(x, y);
    return *(uint32_t*)&t;
}

// ===========================================================================
// Fused K + V projection: fp32 compute, split fp16 output.
// K: hi+lo row-major. V: hi only, transposed [b][feat][key].
// ===========================================================================
__global__ __launch_bounds__(256) void projkv_kernel(
    const float* __restrict__ kv,
    const float* __restrict__ Wk, const float* __restrict__ Wv,
    __half* __restrict__ okh, __half* __restrict__ okl,
    __half* __restrict__ ovh)
{
    __shared__ float sWk[NF_ * NF_];
    __shared__ float sWv[NF_ * NF_];
    __shared__ float sIn[64 * NF_];
    const int tid = threadIdx.x;
    const long long r0 = (long long)blockIdx.x * 64;

    #pragma unroll
    for (int j = 0; j < 4; j++) {
        ((float4*)sWk)[tid + 256 * j] = ((const float4*)Wk)[tid + 256 * j];
        ((float4*)sWv)[tid + 256 * j] = ((const float4*)Wv)[tid + 256 * j];
        ((float4*)sIn)[tid + 256 * j] = ((const float4*)(kv + r0 * NF_))[tid + 256 * j];
    }
    __syncthreads();

    const int rq = tid >> 4, tx = tid & 15;

    #pragma unroll
    for (int which = 0; which < 2; which++) {
        const float* sW = which ? sWv : sWk;
        float acc[4][4];
        #pragma unroll
        for (int i = 0; i < 4; i++)
            #pragma unroll
            for (int j = 0; j < 4; j++) acc[i][j] = 0.f;

        #pragma unroll
        for (int d4 = 0; d4 < 16; d4++) {
            float4 av[4], wv[4];
            #pragma unroll
            for (int i = 0; i < 4; i++) av[i] = *(const float4*)&sIn[(rq * 4 + i) * NF_ + d4 * 4];
            #pragma unroll
            for (int dd = 0; dd < 4; dd++) wv[dd] = *(const float4*)&sW[(d4 * 4 + dd) * NF_ + tx * 4];
            #pragma unroll
            for (int i = 0; i < 4; i++) {
                const float* af = (const float*)&av[i];
                #pragma unroll
                for (int dd = 0; dd < 4; dd++) {
                    const float* wf = (const float*)&wv[dd];
                    #pragma unroll
                    for (int j = 0; j < 4; j++)
                        acc[i][j] = fmaf(af[dd], wf[j], acc[i][j]);
                }
            }
        }

        #pragma unroll
        for (int i = 0; i < 4; i++) {
            const long long row = r0 + rq * 4 + i;
            if (which == 0) {
                uint2 hw, lw;
                __half h0 = __float2half_rn(acc[i][0]), h1 = __float2half_rn(acc[i][1]);
                __half h2 = __float2half_rn(acc[i][2]), h3 = __float2half_rn(acc[i][3]);
                hw.x = pack2h(acc[i][0], acc[i][1]);
                hw.y = pack2h(acc[i][2], acc[i][3]);
                lw.x = pack2h(acc[i][0] - __half2float(h0), acc[i][1] - __half2float(h1));
                lw.y = pack2h(acc[i][2] - __half2float(h2), acc[i][3] - __half2float(h3));
                *(uint2*)(okh + row * NF_ + tx * 4) = hw;
                *(uint2*)(okl + row * NF_ + tx * 4) = lw;
            } else {
                const long long b   = row >> 10;
                const long long key = row & 1023;
                #pragma unroll
                for (int j = 0; j < 4; j++) {
                    const long long idx = (b * NF_ + (tx * 4 + j)) * LK_ + key;
                    ovh[idx] = __float2half_rn(acc[i][j]);
                }
            }
        }
    }
}

// ===========================================================================
// Fused q-proj + flash attention, M=32 rows per warp.  (R15 design, re-bench)
// CTA: 128 threads = 4 warps; warp w owns query rows w*32..w*32+31
// (two 16-row MMA groups mh=0,1). Each K/V B-fragment feeds both groups:
// smem read bytes per MAC halved vs M=16.
// q pre-scaled by log2(e); softmax in exp2 domain, per-32-key chunks.
// S = qh*kh + qh*kl + ql*kh; PV = ph*vh.
// Smem (80KB/CTA, 2 CTAs/SM):
//   [0,16K) QH frags  [16,32K) QL frags  (layout: [kc][g*32+lane] 16B)
//   [32,56K) buffer 0 (KH/KL/VH 8KB each); [56,80K) buffer 1
//   prologue reuse: x staging at 32K (32KB), Wq at 64K (16KB)
// ===========================================================================
#define OFF_QHF 0
#define OFF_QLF 16384
#define OFF_BUF 32768
#define BUF_BYTES 24576
#define OFF_KH 0
#define OFF_KL 8192
#define OFF_VH 16384
#define SMEM_TOTAL 81920

__global__ __launch_bounds__(128, 2) void attn_fused_kernel(
    const float* __restrict__ x, const float* __restrict__ Wq,
    const __half* __restrict__ kh, const __half* __restrict__ kl,
    const __half* __restrict__ vth,
    float* __restrict__ out)
{
    extern __shared__ char smem[];
    const uint32_t sb = smem_u32(smem);
    const int tid  = threadIdx.x;          // 0..127
    const int w    = tid >> 5;             // 0..3
    const int lane = tid & 31;
    const int b    = blockIdx.x >> 6;
    const int q0   = (blockIdx.x & 63) * 128;

    // ---------------- prologue: q = (x * Wq) * log2e, split to frag smem ----
    {
        const char* gx = (const char*)(x + ((size_t)b * LQ_ + q0) * NF_);
        #pragma unroll
        for (int j = 0; j < 16; j++) {
            const int c = tid + 128 * j;               // 0..2047 (x: 32KB)
            cp16(sb + OFF_BUF + (uint32_t)c * 16, gx + (size_t)c * 16);
        }
        #pragma unroll
        for (int j = 0; j < 8; j++) {
            const int c = tid + 128 * j;               // 0..1023 (Wq: 16KB)
            cp16(sb + OFF_BUF + 32768 + (uint32_t)c * 16, (const char*)Wq + (size_t)c * 16);
        }
        CP_COMMIT();
        CP_WAIT0();
        __syncthreads();

        const float* sIn = (const float*)(smem + OFF_BUF);
        const float* sW  = (const float*)(smem + OFF_BUF + 32768);
        const int rq = tid >> 4, tx = tid & 15;        // rq 0..7

        #pragma unroll
        for (int rr = 0; rr < 4; rr++) {               // 32 rows per pass
            float acc[4][4];
            #pragma unroll
            for (int i = 0; i < 4; i++)
                #pragma unroll
                for (int j = 0; j < 4; j++) acc[i][j] = 0.f;

            #pragma unroll
            for (int d4 = 0; d4 < 16; d4++) {
                float4 av[4], wv[4];
                #pragma unroll
                for (int i = 0; i < 4; i++)
                    av[i] = *(const float4*)&sIn[(rr * 32 + rq * 4 + i) * NF_ + d4 * 4];
                #pragma unroll
                for (int dd = 0; dd < 4; dd++)
                    wv[dd] = *(const float4*)&sW[(d4 * 4 + dd) * NF_ + tx * 4];
                #pragma unroll
                for (int i = 0; i < 4; i++) {
                    const float* af = (const float*)&av[i];
                    #pragma unroll
                    for (int dd = 0; dd < 4; dd++) {
                        const float* wf = (const float*)&wv[dd];
                        #pragma unroll
                        for (int j = 0; j < 4; j++)
                            acc[i][j] = fmaf(af[dd], wf[j], acc[i][j]);
                    }
                }
            }
            // scale to exp2 domain, split into fp16 hi/lo fragments
            #pragma unroll
            for (int i = 0; i < 4; i++) {
                const int row = rr * 32 + rq * 4 + i;
                #pragma unroll
                for (int j = 0; j < 4; j++) {
                    const int col = tx * 4 + j;
                    const float a = acc[i][j] * LOG2E;
                    const __half h = __float2half_rn(a);
                    const __half l = __float2half_rn(a - __half2float(h));
                    const int kc  = col >> 4;
                    const int c4  = col & 15;
                    const int idx = ((row >> 3) & 1) | ((c4 >> 3) << 1);
                    const int tf  = ((row >> 4) << 5) | (((row & 7) << 2) | ((c4 & 7) >> 1));
                    const uint32_t off = (uint32_t)(kc * 4096 + tf * 16 + idx * 4 + (c4 & 1) * 2);
                    *(__half*)(smem + OFF_QHF + off) = h;
                    *(__half*)(smem + OFF_QLF + off) = l;
                }
            }
        }
        __syncthreads();   // frags visible; staging areas now reusable
    }

    // ---- persistent Q hi/lo fragments for BOTH 16-row groups of this warp --
    uint32_t qhf[4][8], qlf[4][8];
    #pragma unroll
    for (int kc = 0; kc < 4; kc++) {
        #pragma unroll
        for (int mh = 0; mh < 2; mh++) {
            const uint32_t fo = (uint32_t)(kc * 4096 + ((2 * w + mh) * 32 + lane) * 16);
            uint4 t0 = *(const uint4*)(smem + OFF_QHF + fo);
            qhf[kc][mh * 4 + 0] = t0.x; qhf[kc][mh * 4 + 1] = t0.y;
            qhf[kc][mh * 4 + 2] = t0.z; qhf[kc][mh * 4 + 3] = t0.w;
            uint4 t1 = *(const uint4*)(smem + OFF_QLF + fo);
            qlf[kc][mh * 4 + 0] = t1.x; qlf[kc][mh * 4 + 1] = t1.y;
            qlf[kc][mh * 4 + 2] = t1.z; qlf[kc][mh * 4 + 3] = t1.w;
        }
    }

    // ---- K/V tile loader (cp.async, swizzled) ----
    const char* gkh = (const char*)(kh  + (size_t)b * LK_ * NF_);
    const char* gkl = (const char*)(kl  + (size_t)b * LK_ * NF_);
    const char* gvh = (const char*)(vth + (size_t)b * NF_ * LK_);

    auto load_tile = [&](int t, int buf) {
        const uint32_t bb = sb + OFF_BUF + (uint32_t)buf * BUF_BYTES;
        #pragma unroll
        for (int j = 0; j < 4; j++) {
            const int c  = tid + j * 128;          // 0..511
            const int r  = c >> 3, ch = c & 7;
            const uint32_t sw = (uint32_t)(r * 128 + ((ch * 16) ^ ((r & 7) << 4)));
            const size_t koff = ((size_t)(t * 64 + r) * NF_ + ch * 8) * 2;
            const size_t voff = ((size_t)r * LK_ + t * 64 + ch * 8) * 2;
            cp16(bb + OFF_KH + sw, gkh + koff);
            cp16(bb + OFF_KL + sw, gkl + koff);
            cp16(bb + OFF_VH + sw, gvh + voff);
        }
    };

    load_tile(0, 0);
    CP_COMMIT();

    float o_acc[2][8][4];
    #pragma unroll
    for (int mh = 0; mh < 2; mh++)
        #pragma unroll
        for (int n = 0; n < 8; n++)
            #pragma unroll
            for (int j = 0; j < 4; j++) o_acc[mh][n][j] = 0.f;
    float lsum[2][2] = {{0.f, 0.f}, {0.f, 0.f}};
    float mrun[2][2] = {{-1e30f, -1e30f}, {-1e30f, -1e30f}};

    const int ln7 = lane & 7;
    const int c0  = lane >> 3;                 // 0..3 (chunk select for ldmatrix)
    const uint32_t krowoff = (uint32_t)(ln7 * 128 + ((c0 * 16) ^ (ln7 << 4)));
    const int vrow_base = ((lane >> 4) << 3) + ln7;
    const int vchunk_sel = (lane >> 3) & 1;

    for (int i = 0; i < NTILE; i++) {
        CP_WAIT0();                            // tile i landed
        __syncthreads();                       // + all warps done with iter i-1
        if (i + 1 < NTILE) { load_tile(i + 1, (i + 1) & 1); CP_COMMIT(); }

        const uint32_t bb  = sb + OFF_BUF + (uint32_t)(i & 1) * BUF_BYTES;
        const uint32_t bKh = bb + OFF_KH, bKl = bb + OFF_KL, bVh = bb + OFF_VH;

        #pragma unroll
        for (int half64 = 0; half64 < 2; half64++) {   // 32-key chunks
            // ---- S: 4 n-tiles x 2 M-groups ----
            float s[2][4][4];
            #pragma unroll
            for (int nn = 0; nn < 4; nn++) {
                const int n = half64 * 4 + nn;
                const uint32_t ka = (uint32_t)(n * 1024) + krowoff;
                uint32_t kh8[8], kl8[8];
                LDMX4(kh8,     bKh + ka);
                LDMX4(kh8 + 4, (bKh + ka) ^ 64u);
                LDMX4(kl8,     bKl + ka);
                LDMX4(kl8 + 4, (bKl + ka) ^ 64u);
                #pragma unroll
                for (int mh = 0; mh < 2; mh++) {
                    float* sp = s[mh][nn];
                    sp[0] = sp[1] = sp[2] = sp[3] = 0.f;
                    #pragma unroll
                    for (int kc = 0; kc < 4; kc++) {
                        mma16816h(sp, &qhf[kc][mh * 4], &kh8[2 * kc]);
                        mma16816h(sp, &qhf[kc][mh * 4], &kl8[2 * kc]);
                        mma16816h(sp, &qlf[kc][mh * 4], &kh8[2 * kc]);
                    }
                }
            }
            // ---- online softmax per 32-key chunk (both M-groups) ----
            uint32_t ph[2][2][4];
            #pragma unroll
            for (int mh = 0; mh < 2; mh++) {
                float t0 = fmaxf(s[mh][0][0], s[mh][0][1]);
                float t1 = fmaxf(s[mh][0][2], s[mh][0][3]);
                #pragma unroll
                for (int nn = 1; nn < 4; nn++) {
                    t0 = fmaxf(t0, fmaxf(s[mh][nn][0], s[mh][nn][1]));
                    t1 = fmaxf(t1, fmaxf(s[mh][nn][2], s[mh][nn][3]));
                }
                t0 = fmaxf(t0, __shfl_xor_sync(0xffffffffu, t0, 1));
                t0 = fmaxf(t0, __shfl_xor_sync(0xffffffffu, t0, 2));
                t1 = fmaxf(t1, __shfl_xor_sync(0xffffffffu, t1, 1));
                t1 = fmaxf(t1, __shfl_xor_sync(0xffffffffu, t1, 2));
                const float mn0 = fmaxf(mrun[mh][0], t0);
                const float mn1 = fmaxf(mrun[mh][1], t1);
                const int changed = (mn0 > mrun[mh][0]) | (mn1 > mrun[mh][1]);
                if (__any_sync(0xffffffffu, changed)) {
                    const float sc0 = exp2f(mrun[mh][0] - mn0);
                    const float sc1 = exp2f(mrun[mh][1] - mn1);
                    mrun[mh][0] = mn0; mrun[mh][1] = mn1;
                    lsum[mh][0] *= sc0; lsum[mh][1] *= sc1;
                    #pragma unroll
                    for (int n = 0; n < 8; n++) {
                        o_acc[mh][n][0] *= sc0; o_acc[mh][n][1] *= sc0;
                        o_acc[mh][n][2] *= sc1; o_acc[mh][n][3] *= sc1;
                    }
                }
                #pragma unroll
                for (int nn = 0; nn < 4; nn++) {
                    const float p0 = exp2f(s[mh][nn][0] - mrun[mh][0]);
                    const float p1 = exp2f(s[mh][nn][1] - mrun[mh][0]);
                    const float p2 = exp2f(s[mh][nn][2] - mrun[mh][1]);
                    const float p3 = exp2f(s[mh][nn][3] - mrun[mh][1]);
                    lsum[mh][0] += p0 + p1;
                    lsum[mh][1] += p2 + p3;
                    const int tt = nn >> 1, hh = nn & 1;
                    ph[mh][tt][hh * 2 + 0] = pack2h(p0, p1);
                    ph[mh][tt][hh * 2 + 1] = pack2h(p2, p3);
                }
            }
            // ---- O += P * V (V frags shared by both M-groups) ----
            #pragma unroll
            for (int tt = 0; tt < 2; tt++) {
                const int ch = 2 * (half64 * 2 + tt) + vchunk_sel;
                #pragma unroll
                for (int p = 0; p < 4; p++) {
                    const int vrow = p * 16 + vrow_base;
                    const uint32_t va = (uint32_t)(vrow * 128 + ((ch * 16) ^ (ln7 << 4)));
                    uint32_t vh4[4];
                    LDMX4(vh4, bVh + va);
                    #pragma unroll
                    for (int mh = 0; mh < 2; mh++) {
                        mma16816h(o_acc[mh][2 * p],     ph[mh][tt], &vh4[0]);
                        mma16816h(o_acc[mh][2 * p + 1], ph[mh][tt], &vh4[2]);
                    }
                }
            }
        }
    }

    // ---- finalize: reduce l over the 4-lane row group, divide, store ----
    #pragma unroll
    for (int mh = 0; mh < 2; mh++) {
        float l0 = lsum[mh][0], l1 = lsum[mh][1];
        l0 += __shfl_xor_sync(0xffffffffu, l0, 1);
        l0 += __shfl_xor_sync(0xffffffffu, l0, 2);
        l1 += __shfl_xor_sync(0xffffffffu, l1, 1);
        l1 += __shfl_xor_sync(0xffffffffu, l1, 2);
        const float inv0 = 1.f / l0;
        const float inv1 = 1.f / l1;

        const size_t gr0 = (size_t)b * LQ_ + q0 + w * 32 + mh * 16 + (lane >> 2);
        const size_t gr1 = gr0 + 8;
        #pragma unroll
        for (int n = 0; n < 8; n++) {
            const int col = n * 8 + (lane & 3) * 2;
            float2 v0, v1;
            v0.x = o_acc[mh][n][0] * inv0; v0.y = o_acc[mh][n][1] * inv0;
            v1.x = o_acc[mh][n][2] * inv1; v1.y = o_acc[mh][n][3] * inv1;
            *(float2*)(out + gr0 * NF_ + col) = v0;
            *(float2*)(out + gr1 * NF_ + col) = v1;
        }
    }
}

// ===========================================================================
// Launch. Inputs (metadata order): x[B,LQ,NF], kv[B,LK,NF], Wq, Wk, Wv.
// ===========================================================================
extern "C" void kernel_launch(void* const* d_in, const int* in_sizes, int n_in,
                              void* d_out, int out_size)
{
    const float* x  = (const float*)d_in[0];
    const float* kv = (const float*)d_in[1];
    const float* Wq = (const float*)d_in[2];
    const float* Wk = (const float*)d_in[3];
    const float* Wv = (const float*)d_in[4];
    float* out = (float*)d_out;

    __half *kh, *kl, *vth;
    cudaGetSymbolAddress((void**)&kh,  g_kh);
    cudaGetSymbolAddress((void**)&kl,  g_kl);
    cudaGetSymbolAddress((void**)&vth, g_vth);

    cudaFuncSetAttribute(attn_fused_kernel,
                         cudaFuncAttributeMaxDynamicSharedMemorySize, SMEM_TOTAL);

    projkv_kernel<<<(B_ * LK_) / 64, 256>>>(kv, Wk, Wv, kh, kl, vth);

    attn_fused_kernel<<<B_ * (LQ_ / 128), 128, SMEM_TOTAL>>>(x, Wq, kh, kl, vth, out);
}